// round 13
// baseline (speedup 1.0000x reference)
#include <cuda_runtime.h>
#include <cuda_bf16.h>
#include <math.h>
#include <stdint.h>

// Problem constants (fixed by the dataset)
#define Bt      16384
#define Dd      256
#define Hh      512
#define Ee      8
#define Kk      2
#define TILE_M  128
#define ROWS_CAP (Bt*Kk + Ee*TILE_M)     // 33792
#define MAX_TILES (ROWS_CAP / TILE_M)    // 264

// A/B SMEM tile: 128 rows x 32 words, stride 36 (bank-conflict-free frags)
#define KCH     32
#define LDT     36
#define TILE_F  (TILE_M * LDT)           // 4608 words per tile

// ---------------- scratch (all tf32 bit patterns stored as uint32) ----------------
__device__ uint32_t g_xt[(size_t)Bt * Dd];
__device__ uint32_t g_wgt[(size_t)Ee * 2 * Hh * Dd];
__device__ uint32_t g_act[(size_t)ROWS_CAP * Hh];
__device__ uint32_t g_wlt[(size_t)Ee * Dd * Hh];     // wl transposed: [e][d][f]
__device__ int      g_tok[ROWS_CAP];
__device__ float    g_wrow[ROWS_CAP];
__device__ int      g_choice[Bt * Kk];
__device__ float    g_weight[Bt * Kk];
__device__ int      g_counts[Ee];
__device__ int      g_cursor[Ee];
__device__ int      g_pstart[Ee + 1];

// ---------------- helpers ----------------
__device__ __forceinline__ float gelu_tanh(float v) {
    const float c = 0.7978845608028654f;
    float t = tanhf(c * (v + 0.044715f * v * v * v));
    return 0.5f * v * (1.f + t);
}
__device__ __forceinline__ uint32_t f2tf32(float f) {
    uint32_t r;
    asm("cvt.rna.tf32.f32 %0, %1;" : "=r"(r) : "f"(f));
    return r;
}
__device__ __forceinline__ void mma_tf32(float* c, const uint32_t* a, const uint32_t* b) {
    asm volatile(
        "mma.sync.aligned.m16n8k8.row.col.f32.tf32.tf32.f32 "
        "{%0,%1,%2,%3}, {%4,%5,%6,%7}, {%8,%9}, {%0,%1,%2,%3};"
        : "+f"(c[0]), "+f"(c[1]), "+f"(c[2]), "+f"(c[3])
        : "r"(a[0]), "r"(a[1]), "r"(a[2]), "r"(a[3]), "r"(b[0]), "r"(b[1]));
}
__device__ __forceinline__ uint32_t smem_u32(const void* p) {
    uint32_t a;
    asm("{ .reg .u64 t; cvta.to.shared.u64 t, %1; cvt.u32.u64 %0, t; }" : "=r"(a) : "l"(p));
    return a;
}
#define CP_ASYNC16(sm, gp) asm volatile("cp.async.cg.shared.global [%0], [%1], 16;" :: "r"(sm), "l"(gp))
#define CP_COMMIT()        asm volatile("cp.async.commit_group;")
#define CP_WAIT(n)         asm volatile("cp.async.wait_group %0;" :: "n"(n))

// ---------------- small kernels ----------------
__global__ void init_kernel() {
    int i = threadIdx.x;
    if (i < Ee) { g_counts[i] = 0; g_cursor[i] = 0; }
}

__global__ void __launch_bounds__(256) router_kernel(const float* __restrict__ x,
                                                     const float* __restrict__ wr,
                                                     const float* __restrict__ rsc) {
    int warp = threadIdx.x >> 5, lane = threadIdx.x & 31;
    int t = blockIdx.x * 8 + warp;
    const float* xr = x + (size_t)t * Dd;
    float sumsq = 0.f;
    float l[8] = {0,0,0,0,0,0,0,0};
#pragma unroll
    for (int i = 0; i < 8; i++) {
        int d = i * 32 + lane;
        float xv = xr[d];
        sumsq += xv * xv;
        float xs = xv * rsc[d];
        float4 w0 = *(const float4*)(wr + d * 8);
        float4 w1 = *(const float4*)(wr + d * 8 + 4);
        l[0] += xs * w0.x; l[1] += xs * w0.y; l[2] += xs * w0.z; l[3] += xs * w0.w;
        l[4] += xs * w1.x; l[5] += xs * w1.y; l[6] += xs * w1.z; l[7] += xs * w1.w;
    }
#pragma unroll
    for (int off = 16; off; off >>= 1) {
        sumsq += __shfl_xor_sync(0xffffffffu, sumsq, off);
#pragma unroll
        for (int e = 0; e < 8; e++) l[e] += __shfl_xor_sync(0xffffffffu, l[e], off);
    }
    if (lane == 0) {
        float s = rsqrtf(sumsq * (1.f / Dd) + 1e-6f) * rsqrtf((float)Dd);
        float lg[8];
#pragma unroll
        for (int e = 0; e < 8; e++) lg[e] = l[e] * s;
        int i1 = 0;
#pragma unroll
        for (int e = 1; e < 8; e++) if (lg[e] > lg[i1]) i1 = e;
        int i2 = (i1 == 0) ? 1 : 0;
#pragma unroll
        for (int e = 0; e < 8; e++) if (e != i1 && e > i2 && lg[e] > lg[i2]) i2 = e;
        float p2 = expf(lg[i2] - lg[i1]);
        float inv = 1.f / (1.f + p2);
        g_choice[2*t] = i1;  g_choice[2*t+1] = i2;
        g_weight[2*t] = inv; g_weight[2*t+1] = p2 * inv;
    }
}

__global__ void __launch_bounds__(256) count_kernel() {
    __shared__ int h[Ee];
    int tid = threadIdx.x;
    if (tid < Ee) h[tid] = 0;
    __syncthreads();
    int base = blockIdx.x * 512 + tid * 2;
    atomicAdd(&h[g_choice[base]], 1);
    atomicAdd(&h[g_choice[base + 1]], 1);
    __syncthreads();
    if (tid < Ee) atomicAdd(&g_counts[tid], h[tid]);
}

__global__ void prefix_kernel() {
    if (threadIdx.x == 0) {
        int p = 0;
#pragma unroll
        for (int e = 0; e < Ee; e++) {
            g_pstart[e] = p;
            p += (g_counts[e] + TILE_M - 1) & ~(TILE_M - 1);
        }
        g_pstart[Ee] = p;
    }
}

__global__ void __launch_bounds__(256) scatter_kernel(const float* __restrict__ pes) {
    __shared__ int scnt[Ee];
    __shared__ int sbase[Ee];
    int tid = threadIdx.x;
    if (tid < Ee) scnt[tid] = 0;
    __syncthreads();
    int t = blockIdx.x * 256 + tid;
    int c0 = g_choice[2*t], c1 = g_choice[2*t + 1];
    int s0 = atomicAdd(&scnt[c0], 1);
    int s1 = atomicAdd(&scnt[c1], 1);
    __syncthreads();
    if (tid < Ee) sbase[tid] = atomicAdd(&g_cursor[tid], scnt[tid]);
    __syncthreads();
    int p0 = g_pstart[c0] + sbase[c0] + s0;
    int p1 = g_pstart[c1] + sbase[c1] + s1;
    g_tok[p0] = t;  g_wrow[p0] = g_weight[2*t]     * pes[c0];
    g_tok[p1] = t;  g_wrow[p1] = g_weight[2*t + 1] * pes[c1];
}

// fp32 -> tf32 preconversion. Destinations are __device__ globals referenced
// DIRECTLY in device code. (Passing a __device__ symbol as a host-side kernel
// argument passes the host shadow address -- that was the 128MiB-guard bug.)
__global__ void __launch_bounds__(256) cvt_x_kernel(const float* __restrict__ src) {
    int i = blockIdx.x * 256 + threadIdx.x;
    float4 v = ((const float4*)src)[i];
    uint4 o;
    o.x = f2tf32(v.x); o.y = f2tf32(v.y); o.z = f2tf32(v.z); o.w = f2tf32(v.w);
    ((uint4*)g_xt)[i] = o;
}
__global__ void __launch_bounds__(256) cvt_wg_kernel(const float* __restrict__ src) {
    int i = blockIdx.x * 256 + threadIdx.x;
    float4 v = ((const float4*)src)[i];
    uint4 o;
    o.x = f2tf32(v.x); o.y = f2tf32(v.y); o.z = f2tf32(v.z); o.w = f2tf32(v.w);
    ((uint4*)g_wgt)[i] = o;
}

// transpose wl (E,H,D) fp32 -> g_wlt (E,D,H) tf32-bits
__global__ void transpose_wl_kernel(const float* __restrict__ wl) {
    __shared__ float tb[32][33];
    int f0 = blockIdx.x * 32, d0 = blockIdx.y * 32, e = blockIdx.z;
    int tx = threadIdx.x, ty = threadIdx.y;
#pragma unroll
    for (int j = 0; j < 4; j++)
        tb[ty + j*8][tx] = wl[((size_t)e * Hh + (f0 + ty + j*8)) * Dd + d0 + tx];
    __syncthreads();
#pragma unroll
    for (int j = 0; j < 4; j++)
        g_wlt[((size_t)e * Dd + d0 + ty + j*8) * Hh + f0 + tx] = f2tf32(tb[tx][ty + j*8]);
}

// ---------------- tile meta ----------------
__device__ __forceinline__ void tile_meta(int row0, int& e_out, int& active_out) {
    int e = -1, active = 0;
    if (row0 < g_pstart[Ee]) {
#pragma unroll
        for (int i = 0; i < Ee; i++)
            if (row0 >= g_pstart[i] && row0 < g_pstart[i + 1]) { e = i; break; }
        active = min(TILE_M, g_counts[e] - (row0 - g_pstart[e]));
    }
    e_out = e; active_out = active;
}

// ---------------- fragment compute (shared by both GEMMs) ----------------
// warp tile 64x32; 8 warps (2 row x 4 col) -> block 128x128
// operands are pre-converted tf32 bits: pure LDS + MMA, zero cvt.
__device__ __forceinline__ void compute_chunk(const uint32_t* __restrict__ As,
                                              const uint32_t* __restrict__ Bs,
                                              int lane, int wr, int wc,
                                              float acc[4][4][4]) {
#pragma unroll
    for (int kk = 0; kk < 4; kk++) {
        int ko = kk * 8;
        uint32_t a[4][4], b[4][2];
#pragma unroll
        for (int mf = 0; mf < 4; mf++) {
            int r0 = wr*64 + mf*16 + (lane >> 2);
            const uint32_t* p0 = As + r0*LDT + ko + (lane & 3);
            a[mf][0] = p0[0];
            a[mf][1] = p0[8*LDT];
            a[mf][2] = p0[4];
            a[mf][3] = p0[8*LDT + 4];
        }
#pragma unroll
        for (int nf = 0; nf < 4; nf++) {
            int c0 = wc*32 + nf*8 + (lane >> 2);
            const uint32_t* p0 = Bs + c0*LDT + ko + (lane & 3);
            b[nf][0] = p0[0];
            b[nf][1] = p0[4];
        }
#pragma unroll
        for (int mf = 0; mf < 4; mf++)
#pragma unroll
            for (int nf = 0; nf < 4; nf++)
                mma_tf32(acc[mf][nf], a[mf], b[nf]);
    }
}

// ==================================================================
// ffn1: rows x Wg^T, virtual N=1024 (vc = f*2 + mat), gelu-gate -> g_act (tf32 bits)
// grid (MAX_TILES, 8); block 256
// ==================================================================
__global__ void __launch_bounds__(256, 2) ffn1_mma() {
    __shared__ int sMeta[2];
    __shared__ int sTok[TILE_M];
    extern __shared__ uint32_t smem[];   // A0 | B0 | A1 | B1 (TILE_F each)

    int tid = threadIdx.x;
    int row0 = blockIdx.x * TILE_M;
    int by = blockIdx.y;
    if (tid == 0) { int e, a; tile_meta(row0, e, a); sMeta[0] = e; sMeta[1] = a; }
    __syncthreads();
    int e = sMeta[0], active = sMeta[1];
    if (active <= 0) return;
    if (tid < TILE_M) sTok[tid] = (tid < active) ? g_tok[row0 + tid] : 0;
    __syncthreads();

    // loader mapping: 2 threads/row, 16 words each (4x 16B)
    int lrow = tid >> 1, lpart = (tid & 1) * 16;
    const uint32_t* xrow = g_xt + (size_t)sTok[lrow] * Dd + lpart;
    int vc = by * TILE_M + lrow;                 // virtual col
    const uint32_t* brow = g_wgt + ((size_t)(e*2 + (vc & 1)) * Hh + (vc >> 1)) * Dd + lpart;
    uint32_t sA = smem_u32(smem) + (uint32_t)(lrow*LDT + lpart) * 4u;
    uint32_t sB = sA + TILE_F * 4u;

    int lane = tid & 31, warp = tid >> 5;
    int wr = warp >> 2, wc = warp & 3;
    float acc[4][4][4];
#pragma unroll
    for (int i = 0; i < 4; i++)
#pragma unroll
        for (int j = 0; j < 4; j++)
#pragma unroll
            for (int q = 0; q < 4; q++) acc[i][j][q] = 0.f;

    const int NCH = Dd / KCH;   // 8
    // prologue
#pragma unroll
    for (int i = 0; i < 4; i++) {
        CP_ASYNC16(sA + i*16, xrow + i*4);
        CP_ASYNC16(sB + i*16, brow + i*4);
    }
    CP_COMMIT();
    for (int s = 0; s < NCH; s++) {
        int buf = s & 1;
        if (s + 1 < NCH) {
            uint32_t dA = smem_u32(smem) + (uint32_t)((1-buf)*2*TILE_F + lrow*LDT + lpart)*4u;
            uint32_t dB = dA + TILE_F * 4u;
            const uint32_t* gx = xrow + (s+1)*KCH;
            const uint32_t* gb = brow + (s+1)*KCH;
#pragma unroll
            for (int i = 0; i < 4; i++) {
                CP_ASYNC16(dA + i*16, gx + i*4);
                CP_ASYNC16(dB + i*16, gb + i*4);
            }
            CP_COMMIT();
            CP_WAIT(1);
        } else {
            CP_WAIT(0);
        }
        __syncthreads();
        const uint32_t* As = smem + buf*2*TILE_F;
        compute_chunk(As, As + TILE_F, lane, wr, wc, acc);
        __syncthreads();
    }

    // epilogue: gelu(even vc)*odd vc -> g_act tf32-bits (garbage rows finite)
    int rbase = row0 + wr*64 + (lane >> 2);
    int fbase = by*64 + wc*16 + (lane & 3);
#pragma unroll
    for (int mf = 0; mf < 4; mf++) {
        int r = rbase + mf*16;
#pragma unroll
        for (int nf = 0; nf < 4; nf++) {
            int f = fbase + nf*4;
            g_act[(size_t)r * Hh + f]     = f2tf32(gelu_tanh(acc[mf][nf][0]) * acc[mf][nf][1]);
            g_act[(size_t)(r+8) * Hh + f] = f2tf32(gelu_tanh(acc[mf][nf][2]) * acc[mf][nf][3]);
        }
    }
}

// ==================================================================
// ffn2: act x wlt[e]^T (128 x 256 x 512), scale, atomic combine into out
// grid (MAX_TILES, 2); block 256
// ==================================================================
__global__ void __launch_bounds__(256, 2) ffn2_mma(float* __restrict__ out) {
    __shared__ int sMeta[2];
    __shared__ int sTok[TILE_M];
    __shared__ float sWr[TILE_M];
    extern __shared__ uint32_t smem[];

    int tid = threadIdx.x;
    int row0 = blockIdx.x * TILE_M;
    int by = blockIdx.y;
    if (tid == 0) { int e, a; tile_meta(row0, e, a); sMeta[0] = e; sMeta[1] = a; }
    __syncthreads();
    int e = sMeta[0], active = sMeta[1];
    if (active <= 0) return;
    if (tid < TILE_M) {
        sTok[tid] = (tid < active) ? g_tok[row0 + tid] : 0;
        sWr[tid]  = (tid < active) ? g_wrow[row0 + tid] : 0.f;
    }
    __syncthreads();

    int lrow = tid >> 1, lpart = (tid & 1) * 16;
    const uint32_t* arow = g_act + (size_t)(row0 + lrow) * Hh + lpart;
    const uint32_t* brow = g_wlt + ((size_t)e * Dd + by*TILE_M + lrow) * Hh + lpart;
    uint32_t sA = smem_u32(smem) + (uint32_t)(lrow*LDT + lpart) * 4u;
    uint32_t sB = sA + TILE_F * 4u;

    int lane = tid & 31, warp = tid >> 5;
    int wr = warp >> 2, wc = warp & 3;
    float acc[4][4][4];
#pragma unroll
    for (int i = 0; i < 4; i++)
#pragma unroll
        for (int j = 0; j < 4; j++)
#pragma unroll
            for (int q = 0; q < 4; q++) acc[i][j][q] = 0.f;

    const int NCH = Hh / KCH;   // 16
#pragma unroll
    for (int i = 0; i < 4; i++) {
        CP_ASYNC16(sA + i*16, arow + i*4);
        CP_ASYNC16(sB + i*16, brow + i*4);
    }
    CP_COMMIT();
    for (int s = 0; s < NCH; s++) {
        int buf = s & 1;
        if (s + 1 < NCH) {
            uint32_t dA = smem_u32(smem) + (uint32_t)((1-buf)*2*TILE_F + lrow*LDT + lpart)*4u;
            uint32_t dB = dA + TILE_F * 4u;
            const uint32_t* ga = arow + (s+1)*KCH;
            const uint32_t* gb = brow + (s+1)*KCH;
#pragma unroll
            for (int i = 0; i < 4; i++) {
                CP_ASYNC16(dA + i*16, ga + i*4);
                CP_ASYNC16(dB + i*16, gb + i*4);
            }
            CP_COMMIT();
            CP_WAIT(1);
        } else {
            CP_WAIT(0);
        }
        __syncthreads();
        const uint32_t* As = smem + buf*2*TILE_F;
        compute_chunk(As, As + TILE_F, lane, wr, wc, acc);
        __syncthreads();
    }

    // epilogue: scale by wrow, atomic add into out (guard inactive rows)
    int rloc = wr*64 + (lane >> 2);
    int dbase = by*TILE_M + wc*32 + (lane & 3)*2;
#pragma unroll
    for (int mf = 0; mf < 4; mf++) {
#pragma unroll
        for (int half = 0; half < 2; half++) {
            int r = rloc + mf*16 + half*8;
            if (r < active) {
                float w = sWr[r];
                float* obase = out + (size_t)sTok[r] * Dd;
#pragma unroll
                for (int nf = 0; nf < 4; nf++) {
                    int d = dbase + nf*8;
                    atomicAdd(obase + d,     acc[mf][nf][half*2]     * w);
                    atomicAdd(obase + d + 1, acc[mf][nf][half*2 + 1] * w);
                }
            }
        }
    }
}

// ---------------- launch ----------------
extern "C" void kernel_launch(void* const* d_in, const int* in_sizes, int n_in,
                              void* d_out, int out_size) {
    const float* x   = (const float*)d_in[0];
    const float* wr  = (const float*)d_in[1];
    const float* wg  = (const float*)d_in[2];
    const float* wl  = (const float*)d_in[3];
    const float* pes = (const float*)d_in[4];
    const float* rsc = (const float*)d_in[5];
    float* out = (float*)d_out;

    const int smemB = 4 * TILE_F * sizeof(uint32_t);   // 73728
    cudaFuncSetAttribute(ffn1_mma, cudaFuncAttributeMaxDynamicSharedMemorySize, smemB);
    cudaFuncSetAttribute(ffn2_mma, cudaFuncAttributeMaxDynamicSharedMemorySize, smemB);

    cudaMemsetAsync(out, 0, (size_t)out_size * sizeof(float), 0);
    init_kernel<<<1, 32>>>();
    router_kernel<<<Bt / 8, 256>>>(x, wr, rsc);
    count_kernel<<<Bt / 256, 256>>>();
    prefix_kernel<<<1, 32>>>();
    scatter_kernel<<<Bt / 256, 256>>>(pes);
    cvt_x_kernel<<<(Bt * Dd / 4) / 256, 256>>>(x);
    cvt_wg_kernel<<<(Ee * 2 * Hh * Dd / 4) / 256, 256>>>(wg);
    transpose_wl_kernel<<<dim3(Hh/32, Dd/32, Ee), dim3(32, 8)>>>(wl);
    ffn1_mma<<<dim3(MAX_TILES, 8), 256, smemB>>>();
    ffn2_mma<<<dim3(MAX_TILES, 2), 256, smemB>>>(out);
}

// round 14
// speedup vs baseline: 1.0005x; 1.0005x over previous
#include <cuda_runtime.h>
#include <cuda_bf16.h>
#include <math.h>
#include <stdint.h>

// Problem constants (fixed by the dataset)
#define Bt      16384
#define Dd      256
#define Hh      512
#define Ee      8
#define Kk      2
#define TILE_M  128
#define ROWS_CAP (Bt*Kk + Ee*TILE_M)     // 33792
#define MAX_TILES (ROWS_CAP / TILE_M)    // 264

// A/B SMEM tile: 128 rows x 32 words, stride 36 (bank-conflict-free frags)
#define KCH     32
#define LDT     36
#define TILE_F  (TILE_M * LDT)           // 4608 words per tile

// ---------------- scratch (all tf32 bit patterns stored as uint32) ----------------
__device__ uint32_t g_xt[(size_t)Bt * Dd];
__device__ uint32_t g_wgt[(size_t)Ee * 2 * Hh * Dd];
__device__ uint32_t g_act[(size_t)ROWS_CAP * Hh];
__device__ uint32_t g_wlt[(size_t)Ee * Dd * Hh];     // wl transposed: [e][d][f]
__device__ int      g_tok[ROWS_CAP];
__device__ float    g_wrow[ROWS_CAP];
__device__ int      g_choice[Bt * Kk];
__device__ float    g_weight[Bt * Kk];
__device__ int      g_counts[Ee];
__device__ int      g_cursor[Ee];
__device__ int      g_pstart[Ee + 1];

// ---------------- helpers ----------------
__device__ __forceinline__ float gelu_tanh(float v) {
    const float c = 0.7978845608028654f;
    float t = tanhf(c * (v + 0.044715f * v * v * v));
    return 0.5f * v * (1.f + t);
}
__device__ __forceinline__ uint32_t f2tf32(float f) {
    uint32_t r;
    asm("cvt.rna.tf32.f32 %0, %1;" : "=r"(r) : "f"(f));
    return r;
}
__device__ __forceinline__ void mma_tf32(float* c, const uint32_t* a, const uint32_t* b) {
    asm volatile(
        "mma.sync.aligned.m16n8k8.row.col.f32.tf32.tf32.f32 "
        "{%0,%1,%2,%3}, {%4,%5,%6,%7}, {%8,%9}, {%0,%1,%2,%3};"
        : "+f"(c[0]), "+f"(c[1]), "+f"(c[2]), "+f"(c[3])
        : "r"(a[0]), "r"(a[1]), "r"(a[2]), "r"(a[3]), "r"(b[0]), "r"(b[1]));
}
__device__ __forceinline__ uint32_t smem_u32(const void* p) {
    uint32_t a;
    asm("{ .reg .u64 t; cvta.to.shared.u64 t, %1; cvt.u32.u64 %0, t; }" : "=r"(a) : "l"(p));
    return a;
}
#define CP_ASYNC16(sm, gp) asm volatile("cp.async.cg.shared.global [%0], [%1], 16;" :: "r"(sm), "l"(gp))
#define CP_COMMIT()        asm volatile("cp.async.commit_group;")
#define CP_WAIT(n)         asm volatile("cp.async.wait_group %0;" :: "n"(n))

// ---------------- small kernels ----------------
__global__ void init_kernel() {
    int i = threadIdx.x;
    if (i < Ee) { g_counts[i] = 0; g_cursor[i] = 0; }
}

__global__ void __launch_bounds__(256) router_kernel(const float* __restrict__ x,
                                                     const float* __restrict__ wr,
                                                     const float* __restrict__ rsc) {
    int warp = threadIdx.x >> 5, lane = threadIdx.x & 31;
    int t = blockIdx.x * 8 + warp;
    const float* xr = x + (size_t)t * Dd;
    float sumsq = 0.f;
    float l[8] = {0,0,0,0,0,0,0,0};
#pragma unroll
    for (int i = 0; i < 8; i++) {
        int d = i * 32 + lane;
        float xv = xr[d];
        sumsq += xv * xv;
        float xs = xv * rsc[d];
        float4 w0 = *(const float4*)(wr + d * 8);
        float4 w1 = *(const float4*)(wr + d * 8 + 4);
        l[0] += xs * w0.x; l[1] += xs * w0.y; l[2] += xs * w0.z; l[3] += xs * w0.w;
        l[4] += xs * w1.x; l[5] += xs * w1.y; l[6] += xs * w1.z; l[7] += xs * w1.w;
    }
#pragma unroll
    for (int off = 16; off; off >>= 1) {
        sumsq += __shfl_xor_sync(0xffffffffu, sumsq, off);
#pragma unroll
        for (int e = 0; e < 8; e++) l[e] += __shfl_xor_sync(0xffffffffu, l[e], off);
    }
    if (lane == 0) {
        float s = rsqrtf(sumsq * (1.f / Dd) + 1e-6f) * rsqrtf((float)Dd);
        float lg[8];
#pragma unroll
        for (int e = 0; e < 8; e++) lg[e] = l[e] * s;
        int i1 = 0;
#pragma unroll
        for (int e = 1; e < 8; e++) if (lg[e] > lg[i1]) i1 = e;
        int i2 = (i1 == 0) ? 1 : 0;
#pragma unroll
        for (int e = 0; e < 8; e++) if (e != i1 && e > i2 && lg[e] > lg[i2]) i2 = e;
        float p2 = expf(lg[i2] - lg[i1]);
        float inv = 1.f / (1.f + p2);
        g_choice[2*t] = i1;  g_choice[2*t+1] = i2;
        g_weight[2*t] = inv; g_weight[2*t+1] = p2 * inv;
    }
}

__global__ void __launch_bounds__(256) count_kernel() {
    __shared__ int h[Ee];
    int tid = threadIdx.x;
    if (tid < Ee) h[tid] = 0;
    __syncthreads();
    int base = blockIdx.x * 512 + tid * 2;
    atomicAdd(&h[g_choice[base]], 1);
    atomicAdd(&h[g_choice[base + 1]], 1);
    __syncthreads();
    if (tid < Ee) atomicAdd(&g_counts[tid], h[tid]);
}

__global__ void prefix_kernel() {
    if (threadIdx.x == 0) {
        int p = 0;
#pragma unroll
        for (int e = 0; e < Ee; e++) {
            g_pstart[e] = p;
            p += (g_counts[e] + TILE_M - 1) & ~(TILE_M - 1);
        }
        g_pstart[Ee] = p;
    }
}

__global__ void __launch_bounds__(256) scatter_kernel(const float* __restrict__ pes) {
    __shared__ int scnt[Ee];
    __shared__ int sbase[Ee];
    int tid = threadIdx.x;
    if (tid < Ee) scnt[tid] = 0;
    __syncthreads();
    int t = blockIdx.x * 256 + tid;
    int c0 = g_choice[2*t], c1 = g_choice[2*t + 1];
    int s0 = atomicAdd(&scnt[c0], 1);
    int s1 = atomicAdd(&scnt[c1], 1);
    __syncthreads();
    if (tid < Ee) sbase[tid] = atomicAdd(&g_cursor[tid], scnt[tid]);
    __syncthreads();
    int p0 = g_pstart[c0] + sbase[c0] + s0;
    int p1 = g_pstart[c1] + sbase[c1] + s1;
    g_tok[p0] = t;  g_wrow[p0] = g_weight[2*t]     * pes[c0];
    g_tok[p1] = t;  g_wrow[p1] = g_weight[2*t + 1] * pes[c1];
}

// fp32 -> tf32 preconversion. Destinations are __device__ globals referenced
// DIRECTLY in device code. (Passing a __device__ symbol as a host-side kernel
// argument passes the host shadow address -- that was the 128MiB-guard bug.)
__global__ void __launch_bounds__(256) cvt_x_kernel(const float* __restrict__ src) {
    int i = blockIdx.x * 256 + threadIdx.x;
    float4 v = ((const float4*)src)[i];
    uint4 o;
    o.x = f2tf32(v.x); o.y = f2tf32(v.y); o.z = f2tf32(v.z); o.w = f2tf32(v.w);
    ((uint4*)g_xt)[i] = o;
}
__global__ void __launch_bounds__(256) cvt_wg_kernel(const float* __restrict__ src) {
    int i = blockIdx.x * 256 + threadIdx.x;
    float4 v = ((const float4*)src)[i];
    uint4 o;
    o.x = f2tf32(v.x); o.y = f2tf32(v.y); o.z = f2tf32(v.z); o.w = f2tf32(v.w);
    ((uint4*)g_wgt)[i] = o;
}

// transpose wl (E,H,D) fp32 -> g_wlt (E,D,H) tf32-bits
__global__ void transpose_wl_kernel(const float* __restrict__ wl) {
    __shared__ float tb[32][33];
    int f0 = blockIdx.x * 32, d0 = blockIdx.y * 32, e = blockIdx.z;
    int tx = threadIdx.x, ty = threadIdx.y;
#pragma unroll
    for (int j = 0; j < 4; j++)
        tb[ty + j*8][tx] = wl[((size_t)e * Hh + (f0 + ty + j*8)) * Dd + d0 + tx];
    __syncthreads();
#pragma unroll
    for (int j = 0; j < 4; j++)
        g_wlt[((size_t)e * Dd + d0 + ty + j*8) * Hh + f0 + tx] = f2tf32(tb[tx][ty + j*8]);
}

// ---------------- tile meta ----------------
__device__ __forceinline__ void tile_meta(int row0, int& e_out, int& active_out) {
    int e = -1, active = 0;
    if (row0 < g_pstart[Ee]) {
#pragma unroll
        for (int i = 0; i < Ee; i++)
            if (row0 >= g_pstart[i] && row0 < g_pstart[i + 1]) { e = i; break; }
        active = min(TILE_M, g_counts[e] - (row0 - g_pstart[e]));
    }
    e_out = e; active_out = active;
}

// ---------------- fragment compute (shared by both GEMMs) ----------------
// warp tile 64x32; 8 warps (2 row x 4 col) -> block 128x128
// operands are pre-converted tf32 bits: pure LDS + MMA, zero cvt.
__device__ __forceinline__ void compute_chunk(const uint32_t* __restrict__ As,
                                              const uint32_t* __restrict__ Bs,
                                              int lane, int wr, int wc,
                                              float acc[4][4][4]) {
#pragma unroll
    for (int kk = 0; kk < 4; kk++) {
        int ko = kk * 8;
        uint32_t a[4][4], b[4][2];
#pragma unroll
        for (int mf = 0; mf < 4; mf++) {
            int r0 = wr*64 + mf*16 + (lane >> 2);
            const uint32_t* p0 = As + r0*LDT + ko + (lane & 3);
            a[mf][0] = p0[0];
            a[mf][1] = p0[8*LDT];
            a[mf][2] = p0[4];
            a[mf][3] = p0[8*LDT + 4];
        }
#pragma unroll
        for (int nf = 0; nf < 4; nf++) {
            int c0 = wc*32 + nf*8 + (lane >> 2);
            const uint32_t* p0 = Bs + c0*LDT + ko + (lane & 3);
            b[nf][0] = p0[0];
            b[nf][1] = p0[4];
        }
#pragma unroll
        for (int mf = 0; mf < 4; mf++)
#pragma unroll
            for (int nf = 0; nf < 4; nf++)
                mma_tf32(acc[mf][nf], a[mf], b[nf]);
    }
}

// ==================================================================
// ffn1: rows x Wg^T, virtual N=1024 (vc = f*2 + mat), gelu-gate -> g_act (tf32 bits)
// grid (MAX_TILES, 8); block 256
// ==================================================================
__global__ void __launch_bounds__(256, 2) ffn1_mma() {
    __shared__ int sMeta[2];
    __shared__ int sTok[TILE_M];
    extern __shared__ uint32_t smem[];   // A0 | B0 | A1 | B1 (TILE_F each)

    int tid = threadIdx.x;
    int row0 = blockIdx.x * TILE_M;
    int by = blockIdx.y;
    if (tid == 0) { int e, a; tile_meta(row0, e, a); sMeta[0] = e; sMeta[1] = a; }
    __syncthreads();
    int e = sMeta[0], active = sMeta[1];
    if (active <= 0) return;
    if (tid < TILE_M) sTok[tid] = (tid < active) ? g_tok[row0 + tid] : 0;
    __syncthreads();

    // loader mapping: 2 threads/row, 16 words each (4x 16B)
    int lrow = tid >> 1, lpart = (tid & 1) * 16;
    const uint32_t* xrow = g_xt + (size_t)sTok[lrow] * Dd + lpart;
    int vc = by * TILE_M + lrow;                 // virtual col
    const uint32_t* brow = g_wgt + ((size_t)(e*2 + (vc & 1)) * Hh + (vc >> 1)) * Dd + lpart;
    uint32_t sA = smem_u32(smem) + (uint32_t)(lrow*LDT + lpart) * 4u;
    uint32_t sB = sA + TILE_F * 4u;

    int lane = tid & 31, warp = tid >> 5;
    int wr = warp >> 2, wc = warp & 3;
    float acc[4][4][4];
#pragma unroll
    for (int i = 0; i < 4; i++)
#pragma unroll
        for (int j = 0; j < 4; j++)
#pragma unroll
            for (int q = 0; q < 4; q++) acc[i][j][q] = 0.f;

    const int NCH = Dd / KCH;   // 8
    // prologue
#pragma unroll
    for (int i = 0; i < 4; i++) {
        CP_ASYNC16(sA + i*16, xrow + i*4);
        CP_ASYNC16(sB + i*16, brow + i*4);
    }
    CP_COMMIT();
    for (int s = 0; s < NCH; s++) {
        int buf = s & 1;
        if (s + 1 < NCH) {
            uint32_t dA = smem_u32(smem) + (uint32_t)((1-buf)*2*TILE_F + lrow*LDT + lpart)*4u;
            uint32_t dB = dA + TILE_F * 4u;
            const uint32_t* gx = xrow + (s+1)*KCH;
            const uint32_t* gb = brow + (s+1)*KCH;
#pragma unroll
            for (int i = 0; i < 4; i++) {
                CP_ASYNC16(dA + i*16, gx + i*4);
                CP_ASYNC16(dB + i*16, gb + i*4);
            }
            CP_COMMIT();
            CP_WAIT(1);
        } else {
            CP_WAIT(0);
        }
        __syncthreads();
        const uint32_t* As = smem + buf*2*TILE_F;
        compute_chunk(As, As + TILE_F, lane, wr, wc, acc);
        __syncthreads();
    }

    // epilogue: gelu(even vc)*odd vc -> g_act tf32-bits (garbage rows finite)
    int rbase = row0 + wr*64 + (lane >> 2);
    int fbase = by*64 + wc*16 + (lane & 3);
#pragma unroll
    for (int mf = 0; mf < 4; mf++) {
        int r = rbase + mf*16;
#pragma unroll
        for (int nf = 0; nf < 4; nf++) {
            int f = fbase + nf*4;
            g_act[(size_t)r * Hh + f]     = f2tf32(gelu_tanh(acc[mf][nf][0]) * acc[mf][nf][1]);
            g_act[(size_t)(r+8) * Hh + f] = f2tf32(gelu_tanh(acc[mf][nf][2]) * acc[mf][nf][3]);
        }
    }
}

// ==================================================================
// ffn2: act x wlt[e]^T (128 x 256 x 512), scale, atomic combine into out
// grid (MAX_TILES, 2); block 256
// ==================================================================
__global__ void __launch_bounds__(256, 2) ffn2_mma(float* __restrict__ out) {
    __shared__ int sMeta[2];
    __shared__ int sTok[TILE_M];
    __shared__ float sWr[TILE_M];
    extern __shared__ uint32_t smem[];

    int tid = threadIdx.x;
    int row0 = blockIdx.x * TILE_M;
    int by = blockIdx.y;
    if (tid == 0) { int e, a; tile_meta(row0, e, a); sMeta[0] = e; sMeta[1] = a; }
    __syncthreads();
    int e = sMeta[0], active = sMeta[1];
    if (active <= 0) return;
    if (tid < TILE_M) {
        sTok[tid] = (tid < active) ? g_tok[row0 + tid] : 0;
        sWr[tid]  = (tid < active) ? g_wrow[row0 + tid] : 0.f;
    }
    __syncthreads();

    int lrow = tid >> 1, lpart = (tid & 1) * 16;
    const uint32_t* arow = g_act + (size_t)(row0 + lrow) * Hh + lpart;
    const uint32_t* brow = g_wlt + ((size_t)e * Dd + by*TILE_M + lrow) * Hh + lpart;
    uint32_t sA = smem_u32(smem) + (uint32_t)(lrow*LDT + lpart) * 4u;
    uint32_t sB = sA + TILE_F * 4u;

    int lane = tid & 31, warp = tid >> 5;
    int wr = warp >> 2, wc = warp & 3;
    float acc[4][4][4];
#pragma unroll
    for (int i = 0; i < 4; i++)
#pragma unroll
        for (int j = 0; j < 4; j++)
#pragma unroll
            for (int q = 0; q < 4; q++) acc[i][j][q] = 0.f;

    const int NCH = Hh / KCH;   // 16
#pragma unroll
    for (int i = 0; i < 4; i++) {
        CP_ASYNC16(sA + i*16, arow + i*4);
        CP_ASYNC16(sB + i*16, brow + i*4);
    }
    CP_COMMIT();
    for (int s = 0; s < NCH; s++) {
        int buf = s & 1;
        if (s + 1 < NCH) {
            uint32_t dA = smem_u32(smem) + (uint32_t)((1-buf)*2*TILE_F + lrow*LDT + lpart)*4u;
            uint32_t dB = dA + TILE_F * 4u;
            const uint32_t* ga = arow + (s+1)*KCH;
            const uint32_t* gb = brow + (s+1)*KCH;
#pragma unroll
            for (int i = 0; i < 4; i++) {
                CP_ASYNC16(dA + i*16, ga + i*4);
                CP_ASYNC16(dB + i*16, gb + i*4);
            }
            CP_COMMIT();
            CP_WAIT(1);
        } else {
            CP_WAIT(0);
        }
        __syncthreads();
        const uint32_t* As = smem + buf*2*TILE_F;
        compute_chunk(As, As + TILE_F, lane, wr, wc, acc);
        __syncthreads();
    }

    // epilogue: scale by wrow, atomic add into out (guard inactive rows)
    int rloc = wr*64 + (lane >> 2);
    int dbase = by*TILE_M + wc*32 + (lane & 3)*2;
#pragma unroll
    for (int mf = 0; mf < 4; mf++) {
#pragma unroll
        for (int half = 0; half < 2; half++) {
            int r = rloc + mf*16 + half*8;
            if (r < active) {
                float w = sWr[r];
                float* obase = out + (size_t)sTok[r] * Dd;
#pragma unroll
                for (int nf = 0; nf < 4; nf++) {
                    int d = dbase + nf*8;
                    atomicAdd(obase + d,     acc[mf][nf][half*2]     * w);
                    atomicAdd(obase + d + 1, acc[mf][nf][half*2 + 1] * w);
                }
            }
        }
    }
}

// ---------------- launch ----------------
extern "C" void kernel_launch(void* const* d_in, const int* in_sizes, int n_in,
                              void* d_out, int out_size) {
    const float* x   = (const float*)d_in[0];
    const float* wr  = (const float*)d_in[1];
    const float* wg  = (const float*)d_in[2];
    const float* wl  = (const float*)d_in[3];
    const float* pes = (const float*)d_in[4];
    const float* rsc = (const float*)d_in[5];
    float* out = (float*)d_out;

    const int smemB = 4 * TILE_F * sizeof(uint32_t);   // 73728
    cudaFuncSetAttribute(ffn1_mma, cudaFuncAttributeMaxDynamicSharedMemorySize, smemB);
    cudaFuncSetAttribute(ffn2_mma, cudaFuncAttributeMaxDynamicSharedMemorySize, smemB);

    cudaMemsetAsync(out, 0, (size_t)out_size * sizeof(float), 0);
    init_kernel<<<1, 32>>>();
    router_kernel<<<Bt / 8, 256>>>(x, wr, rsc);
    count_kernel<<<Bt / 256, 256>>>();
    prefix_kernel<<<1, 32>>>();
    scatter_kernel<<<Bt / 256, 256>>>(pes);
    cvt_x_kernel<<<(Bt * Dd / 4) / 256, 256>>>(x);
    cvt_wg_kernel<<<(Ee * 2 * Hh * Dd / 4) / 256, 256>>>(wg);
    transpose_wl_kernel<<<dim3(Hh/32, Dd/32, Ee), dim3(32, 8)>>>(wl);
    ffn1_mma<<<dim3(MAX_TILES, 8), 256, smemB>>>();
    ffn2_mma<<<dim3(MAX_TILES, 2), 256, smemB>>>(out);
}

// round 16
// speedup vs baseline: 1.7803x; 1.7793x over previous
#include <cuda_runtime.h>
#include <cuda_fp16.h>
#include <math.h>
#include <stdint.h>

// Problem constants (fixed by the dataset)
#define Bt      16384
#define Dd      256
#define Hh      512
#define Ee      8
#define Kk      2
#define TILE_M  128
#define ROWS_CAP (Bt*Kk + Ee*TILE_M)     // 33792
#define MAX_TILES (ROWS_CAP / TILE_M)    // 264

#define KCH     32                        // K elems per chunk
#define LDH     40                        // smem row stride in halves (conflict-free)
#define TILE_B  (TILE_M * LDH * 2)        // 10240 bytes per tile
#define NSTAGE  3
#define STAGE_B (2 * TILE_B)              // A + B per stage
#define MF_STRIDE (16 * LDH * 2)          // 1280 bytes between A m-fragments

// ---------------- scratch ----------------
__device__ __half g_xh[(size_t)Bt * Dd];
__device__ __half g_wgh[(size_t)Ee * 2 * Hh * Dd];
__device__ __half g_wlth[(size_t)Ee * Dd * Hh];      // wl transposed: [e][d][f], half
__device__ __half g_acth[(size_t)ROWS_CAP * Hh];
__device__ int    g_tok[ROWS_CAP];
__device__ float  g_wrow[ROWS_CAP];
__device__ int    g_choice[Bt * Kk];
__device__ float  g_weight[Bt * Kk];
__device__ int    g_counts[Ee];
__device__ int    g_cursor[Ee];
__device__ int    g_pstart[Ee + 1];

// ---------------- helpers ----------------
__device__ __forceinline__ float gelu_tanh(float v) {
    const float c = 0.7978845608028654f;
    float t = tanhf(c * (v + 0.044715f * v * v * v));
    return 0.5f * v * (1.f + t);
}
__device__ __forceinline__ uint32_t smem_u32(const void* p) {
    uint32_t a;
    asm("{ .reg .u64 t; cvta.to.shared.u64 t, %1; cvt.u32.u64 %0, t; }" : "=r"(a) : "l"(p));
    return a;
}
#define CP_ASYNC16(sm, gp) asm volatile("cp.async.cg.shared.global [%0], [%1], 16;" :: "r"(sm), "l"(gp))
#define CP_COMMIT()        asm volatile("cp.async.commit_group;")
#define CP_WAIT(n)         asm volatile("cp.async.wait_group %0;" :: "n"(n))

#define LDMX4(r0, r1, r2, r3, addr) \
    asm volatile("ldmatrix.sync.aligned.m8n8.x4.shared.b16 {%0,%1,%2,%3}, [%4];" \
        : "=r"(r0), "=r"(r1), "=r"(r2), "=r"(r3) : "r"(addr))

#define MMA4(c, a0, a1, a2, a3, b0, b1) \
    asm volatile("mma.sync.aligned.m16n8k16.row.col.f32.f16.f16.f32 " \
        "{%0,%1,%2,%3},{%4,%5,%6,%7},{%8,%9},{%0,%1,%2,%3};" \
        : "+f"((c).x), "+f"((c).y), "+f"((c).z), "+f"((c).w) \
        : "r"(a0), "r"(a1), "r"(a2), "r"(a3), "r"(b0), "r"(b1))

// one K=16 step: 4 A-ldmatrix + 2 B-ldmatrix + 16 mma, all named scalars
#define K16_COMPUTE(st, k16b) do { \
    uint32_t _sa  = (st) + aoffb + (k16b); \
    uint32_t _sb  = (st) + TILE_B + boffb + (k16b); \
    uint32_t A00,A01,A02,A03, A10,A11,A12,A13, A20,A21,A22,A23, A30,A31,A32,A33; \
    uint32_t B00,B01,B10,B11, B20,B21,B30,B31; \
    LDMX4(A00,A01,A02,A03, _sa); \
    LDMX4(A10,A11,A12,A13, _sa + MF_STRIDE); \
    LDMX4(A20,A21,A22,A23, _sa + 2*MF_STRIDE); \
    LDMX4(A30,A31,A32,A33, _sa + 3*MF_STRIDE); \
    LDMX4(B00,B01,B10,B11, _sb); \
    LDMX4(B20,B21,B30,B31, _sb + MF_STRIDE); \
    MMA4(c00, A00,A01,A02,A03, B00,B01); \
    MMA4(c01, A00,A01,A02,A03, B10,B11); \
    MMA4(c02, A00,A01,A02,A03, B20,B21); \
    MMA4(c03, A00,A01,A02,A03, B30,B31); \
    MMA4(c10, A10,A11,A12,A13, B00,B01); \
    MMA4(c11, A10,A11,A12,A13, B10,B11); \
    MMA4(c12, A10,A11,A12,A13, B20,B21); \
    MMA4(c13, A10,A11,A12,A13, B30,B31); \
    MMA4(c20, A20,A21,A22,A23, B00,B01); \
    MMA4(c21, A20,A21,A22,A23, B10,B11); \
    MMA4(c22, A20,A21,A22,A23, B20,B21); \
    MMA4(c23, A20,A21,A22,A23, B30,B31); \
    MMA4(c30, A30,A31,A32,A33, B00,B01); \
    MMA4(c31, A30,A31,A32,A33, B10,B11); \
    MMA4(c32, A30,A31,A32,A33, B20,B21); \
    MMA4(c33, A30,A31,A32,A33, B30,B31); \
} while (0)

#define DECL_ACC \
    float4 c00 = make_float4(0.f,0.f,0.f,0.f), c01 = c00, c02 = c00, c03 = c00, \
           c10 = c00, c11 = c00, c12 = c00, c13 = c00, \
           c20 = c00, c21 = c00, c22 = c00, c23 = c00, \
           c30 = c00, c31 = c00, c32 = c00, c33 = c00

// ---------------- small kernels ----------------
__global__ void init_kernel() {
    int i = threadIdx.x;
    if (i < Ee) { g_counts[i] = 0; g_cursor[i] = 0; }
}

__global__ void __launch_bounds__(256) router_kernel(const float* __restrict__ x,
                                                     const float* __restrict__ wr,
                                                     const float* __restrict__ rsc) {
    int warp = threadIdx.x >> 5, lane = threadIdx.x & 31;
    int t = blockIdx.x * 8 + warp;
    const float* xr = x + (size_t)t * Dd;
    float sumsq = 0.f;
    float l[8] = {0,0,0,0,0,0,0,0};
#pragma unroll
    for (int i = 0; i < 8; i++) {
        int d = i * 32 + lane;
        float xv = xr[d];
        sumsq += xv * xv;
        float xs = xv * rsc[d];
        float4 w0 = *(const float4*)(wr + d * 8);
        float4 w1 = *(const float4*)(wr + d * 8 + 4);
        l[0] += xs * w0.x; l[1] += xs * w0.y; l[2] += xs * w0.z; l[3] += xs * w0.w;
        l[4] += xs * w1.x; l[5] += xs * w1.y; l[6] += xs * w1.z; l[7] += xs * w1.w;
    }
#pragma unroll
    for (int off = 16; off; off >>= 1) {
        sumsq += __shfl_xor_sync(0xffffffffu, sumsq, off);
#pragma unroll
        for (int e = 0; e < 8; e++) l[e] += __shfl_xor_sync(0xffffffffu, l[e], off);
    }
    if (lane == 0) {
        float s = rsqrtf(sumsq * (1.f / Dd) + 1e-6f) * rsqrtf((float)Dd);
        float lg[8];
#pragma unroll
        for (int e = 0; e < 8; e++) lg[e] = l[e] * s;
        int i1 = 0;
#pragma unroll
        for (int e = 1; e < 8; e++) if (lg[e] > lg[i1]) i1 = e;
        int i2 = (i1 == 0) ? 1 : 0;
#pragma unroll
        for (int e = 0; e < 8; e++) if (e != i1 && e > i2 && lg[e] > lg[i2]) i2 = e;
        float p2 = expf(lg[i2] - lg[i1]);
        float inv = 1.f / (1.f + p2);
        g_choice[2*t] = i1;  g_choice[2*t+1] = i2;
        g_weight[2*t] = inv; g_weight[2*t+1] = p2 * inv;
    }
}

__global__ void __launch_bounds__(256) count_kernel() {
    __shared__ int h[Ee];
    int tid = threadIdx.x;
    if (tid < Ee) h[tid] = 0;
    __syncthreads();
    int base = blockIdx.x * 512 + tid * 2;
    atomicAdd(&h[g_choice[base]], 1);
    atomicAdd(&h[g_choice[base + 1]], 1);
    __syncthreads();
    if (tid < Ee) atomicAdd(&g_counts[tid], h[tid]);
}

__global__ void prefix_kernel() {
    if (threadIdx.x == 0) {
        int p = 0;
#pragma unroll
        for (int e = 0; e < Ee; e++) {
            g_pstart[e] = p;
            p += (g_counts[e] + TILE_M - 1) & ~(TILE_M - 1);
        }
        g_pstart[Ee] = p;
    }
}

__global__ void __launch_bounds__(256) scatter_kernel(const float* __restrict__ pes) {
    __shared__ int scnt[Ee];
    __shared__ int sbase[Ee];
    int tid = threadIdx.x;
    if (tid < Ee) scnt[tid] = 0;
    __syncthreads();
    int t = blockIdx.x * 256 + tid;
    int c0 = g_choice[2*t], c1 = g_choice[2*t + 1];
    int s0 = atomicAdd(&scnt[c0], 1);
    int s1 = atomicAdd(&scnt[c1], 1);
    __syncthreads();
    if (tid < Ee) sbase[tid] = atomicAdd(&g_cursor[tid], scnt[tid]);
    __syncthreads();
    int p0 = g_pstart[c0] + sbase[c0] + s0;
    int p1 = g_pstart[c1] + sbase[c1] + s1;
    g_tok[p0] = t;  g_wrow[p0] = g_weight[2*t]     * pes[c0];
    g_tok[p1] = t;  g_wrow[p1] = g_weight[2*t + 1] * pes[c1];
}

// fp32 -> fp16 preconversion. Destinations are __device__ globals referenced
// DIRECTLY in device code (a __device__ symbol passed as a host-side kernel
// argument decays to the host shadow address -- the confirmed R5-R12 bug).
__global__ void __launch_bounds__(256) cvt_xh_kernel(const float* __restrict__ src) {
    int i = blockIdx.x * 256 + threadIdx.x;   // grid sized exactly: Bt*Dd/4 / 256
    float4 v = ((const float4*)src)[i];
    __half2* d = (__half2*)g_xh;
    d[2*i]   = __floats2half2_rn(v.x, v.y);
    d[2*i+1] = __floats2half2_rn(v.z, v.w);
}
__global__ void __launch_bounds__(256) cvt_wgh_kernel(const float* __restrict__ src) {
    int i = blockIdx.x * 256 + threadIdx.x;   // Ee*2*Hh*Dd/4 / 256
    float4 v = ((const float4*)src)[i];
    __half2* d = (__half2*)g_wgh;
    d[2*i]   = __floats2half2_rn(v.x, v.y);
    d[2*i+1] = __floats2half2_rn(v.z, v.w);
}

// transpose wl (E,H,D) fp32 -> g_wlth (E,D,H) fp16
__global__ void transpose_wl_kernel(const float* __restrict__ wl) {
    __shared__ float tb[32][33];
    int f0 = blockIdx.x * 32, d0 = blockIdx.y * 32, e = blockIdx.z;
    int tx = threadIdx.x, ty = threadIdx.y;
#pragma unroll
    for (int j = 0; j < 4; j++)
        tb[ty + j*8][tx] = wl[((size_t)e * Hh + (f0 + ty + j*8)) * Dd + d0 + tx];
    __syncthreads();
#pragma unroll
    for (int j = 0; j < 4; j++)
        g_wlth[((size_t)e * Dd + d0 + ty + j*8) * Hh + f0 + tx] = __float2half(tb[tx][ty + j*8]);
}

// ---------------- tile meta ----------------
__device__ __forceinline__ void tile_meta(int row0, int& e_out, int& active_out) {
    int e = -1, active = 0;
    if (row0 < g_pstart[Ee]) {
#pragma unroll
        for (int i = 0; i < Ee; i++)
            if (row0 >= g_pstart[i] && row0 < g_pstart[i + 1]) { e = i; break; }
        active = min(TILE_M, g_counts[e] - (row0 - g_pstart[e]));
    }
    e_out = e; active_out = active;
}

// ==================================================================
// ffn1: rows x Wg^T (fp16), virtual N=1024 (vc = f*2 + mat), gelu-gate -> g_acth
// grid (MAX_TILES, 8); block 256
// ==================================================================
__global__ void __launch_bounds__(256) ffn1_mma() {
    __shared__ int sMeta[2];
    __shared__ int sTok[TILE_M];
    extern __shared__ __half smem[];   // NSTAGE x (A | B)

    int tid = threadIdx.x;
    int row0 = blockIdx.x * TILE_M;
    int by = blockIdx.y;
    if (tid == 0) { int e, a; tile_meta(row0, e, a); sMeta[0] = e; sMeta[1] = a; }
    __syncthreads();
    int e = sMeta[0], active = sMeta[1];
    if (active <= 0) return;
    if (tid < TILE_M) sTok[tid] = (tid < active) ? g_tok[row0 + tid] : 0;
    __syncthreads();

    // loader mapping: 2 threads/row, 16 halves (32B) each
    int lrow = tid >> 1, lhalf = tid & 1;
    const __half* ag = g_xh + (size_t)sTok[lrow] * Dd + lhalf * 16;
    int vc = by * TILE_M + lrow;
    const __half* bg = g_wgh + ((size_t)(e*2 + (vc & 1)) * Hh + (vc >> 1)) * Dd + lhalf * 16;
    uint32_t sbase = smem_u32(smem);
    uint32_t lodA = (uint32_t)(lrow * LDH + lhalf * 16) * 2;
    uint32_t lodB = lodA + TILE_B;

    int lane = tid & 31, warp = tid >> 5;
    int wr = warp >> 2, wc = warp & 3;
    uint32_t aoffb = (uint32_t)(((wr*64 + (lane & 15)) * LDH + (lane >> 4) * 8) * 2);
    uint32_t boffb = (uint32_t)(((wc*32 + ((lane >> 4) & 1) * 8 + (lane & 7)) * LDH
                                 + ((lane >> 3) & 1) * 8) * 2);
    DECL_ACC;

    const int NCH = Dd / KCH;   // 8
#pragma unroll
    for (int p = 0; p < 2; p++) {
        uint32_t st = sbase + p * STAGE_B;
        CP_ASYNC16(st + lodA,      ag + p*KCH);
        CP_ASYNC16(st + lodA + 16, ag + p*KCH + 8);
        CP_ASYNC16(st + lodB,      bg + p*KCH);
        CP_ASYNC16(st + lodB + 16, bg + p*KCH + 8);
        CP_COMMIT();
    }
    for (int s = 0; s < NCH; s++) {
        if (s + 1 < NCH) { CP_WAIT(1); } else { CP_WAIT(0); }
        __syncthreads();
        if (s + 2 < NCH) {
            uint32_t st = sbase + ((s + 2) % NSTAGE) * STAGE_B;
            int k0 = (s + 2) * KCH;
            CP_ASYNC16(st + lodA,      ag + k0);
            CP_ASYNC16(st + lodA + 16, ag + k0 + 8);
            CP_ASYNC16(st + lodB,      bg + k0);
            CP_ASYNC16(st + lodB + 16, bg + k0 + 8);
            CP_COMMIT();
        }
        uint32_t st = sbase + (s % NSTAGE) * STAGE_B;
        K16_COMPUTE(st, 0);
        K16_COMPUTE(st, 32);
    }

    // epilogue: f-col gets gelu(even vc)*odd vc, stored fp16 (garbage rows finite)
    int rbase = row0 + wr*64 + (lane >> 2);
    int fbase = by*64 + wc*16 + (lane & 3);
#define EPI1(c, mf, nf) do { \
        int _r = rbase + (mf)*16; \
        int _f = fbase + (nf)*4; \
        g_acth[(size_t)_r * Hh + _f]       = __float2half(gelu_tanh((c).x) * (c).y); \
        g_acth[(size_t)(_r + 8) * Hh + _f] = __float2half(gelu_tanh((c).z) * (c).w); \
    } while (0)
    EPI1(c00,0,0); EPI1(c01,0,1); EPI1(c02,0,2); EPI1(c03,0,3);
    EPI1(c10,1,0); EPI1(c11,1,1); EPI1(c12,1,2); EPI1(c13,1,3);
    EPI1(c20,2,0); EPI1(c21,2,1); EPI1(c22,2,2); EPI1(c23,2,3);
    EPI1(c30,3,0); EPI1(c31,3,1); EPI1(c32,3,2); EPI1(c33,3,3);
#undef EPI1
}

// ==================================================================
// ffn2: act(h) x wlt[e]^T (128 x 256 x 512), scale, atomic combine into out
// grid (MAX_TILES, 2); block 256
// ==================================================================
__global__ void __launch_bounds__(256) ffn2_mma(float* __restrict__ out) {
    __shared__ int sMeta[2];
    __shared__ int sTok[TILE_M];
    __shared__ float sWr[TILE_M];
    extern __shared__ __half smem[];

    int tid = threadIdx.x;
    int row0 = blockIdx.x * TILE_M;
    int by = blockIdx.y;
    if (tid == 0) { int e, a; tile_meta(row0, e, a); sMeta[0] = e; sMeta[1] = a; }
    __syncthreads();
    int e = sMeta[0], active = sMeta[1];
    if (active <= 0) return;
    if (tid < TILE_M) {
        sTok[tid] = (tid < active) ? g_tok[row0 + tid] : 0;
        sWr[tid]  = (tid < active) ? g_wrow[row0 + tid] : 0.f;
    }
    __syncthreads();

    int lrow = tid >> 1, lhalf = tid & 1;
    const __half* ag = g_acth + (size_t)(row0 + lrow) * Hh + lhalf * 16;
    const __half* bg = g_wlth + ((size_t)e * Dd + by*TILE_M + lrow) * Hh + lhalf * 16;
    uint32_t sbase = smem_u32(smem);
    uint32_t lodA = (uint32_t)(lrow * LDH + lhalf * 16) * 2;
    uint32_t lodB = lodA + TILE_B;

    int lane = tid & 31, warp = tid >> 5;
    int wr = warp >> 2, wc = warp & 3;
    uint32_t aoffb = (uint32_t)(((wr*64 + (lane & 15)) * LDH + (lane >> 4) * 8) * 2);
    uint32_t boffb = (uint32_t)(((wc*32 + ((lane >> 4) & 1) * 8 + (lane & 7)) * LDH
                                 + ((lane >> 3) & 1) * 8) * 2);
    DECL_ACC;

    const int NCH = Hh / KCH;   // 16
#pragma unroll
    for (int p = 0; p < 2; p++) {
        uint32_t st = sbase + p * STAGE_B;
        CP_ASYNC16(st + lodA,      ag + p*KCH);
        CP_ASYNC16(st + lodA + 16, ag + p*KCH + 8);
        CP_ASYNC16(st + lodB,      bg + p*KCH);
        CP_ASYNC16(st + lodB + 16, bg + p*KCH + 8);
        CP_COMMIT();
    }
    for (int s = 0; s < NCH; s++) {
        if (s + 1 < NCH) { CP_WAIT(1); } else { CP_WAIT(0); }
        __syncthreads();
        if (s + 2 < NCH) {
            uint32_t st = sbase + ((s + 2) % NSTAGE) * STAGE_B;
            int k0 = (s + 2) * KCH;
            CP_ASYNC16(st + lodA,      ag + k0);
            CP_ASYNC16(st + lodA + 16, ag + k0 + 8);
            CP_ASYNC16(st + lodB,      bg + k0);
            CP_ASYNC16(st + lodB + 16, bg + k0 + 8);
            CP_COMMIT();
        }
        uint32_t st = sbase + (s % NSTAGE) * STAGE_B;
        K16_COMPUTE(st, 0);
        K16_COMPUTE(st, 32);
    }

    // epilogue: scale by wrow, atomic add into out (guard inactive rows)
    int rloc = wr*64 + (lane >> 2);
    int dbase = by*TILE_M + wc*32 + (lane & 3)*2;
#define EPI2(c, mf, nf) do { \
        int _r1 = rloc + (mf)*16; \
        if (_r1 < active) { \
            float _w = sWr[_r1]; \
            float* _ob = out + (size_t)sTok[_r1] * Dd + dbase + (nf)*8; \
            atomicAdd(_ob,     (c).x * _w); \
            atomicAdd(_ob + 1, (c).y * _w); \
        } \
        int _r2 = _r1 + 8; \
        if (_r2 < active) { \
            float _w = sWr[_r2]; \
            float* _ob = out + (size_t)sTok[_r2] * Dd + dbase + (nf)*8; \
            atomicAdd(_ob,     (c).z * _w); \
            atomicAdd(_ob + 1, (c).w * _w); \
        } \
    } while (0)
    EPI2(c00,0,0); EPI2(c01,0,1); EPI2(c02,0,2); EPI2(c03,0,3);
    EPI2(c10,1,0); EPI2(c11,1,1); EPI2(c12,1,2); EPI2(c13,1,3);
    EPI2(c20,2,0); EPI2(c21,2,1); EPI2(c22,2,2); EPI2(c23,2,3);
    EPI2(c30,3,0); EPI2(c31,3,1); EPI2(c32,3,2); EPI2(c33,3,3);
#undef EPI2
}

// ---------------- launch ----------------
extern "C" void kernel_launch(void* const* d_in, const int* in_sizes, int n_in,
                              void* d_out, int out_size) {
    const float* x   = (const float*)d_in[0];
    const float* wr  = (const float*)d_in[1];
    const float* wg  = (const float*)d_in[2];
    const float* wl  = (const float*)d_in[3];
    const float* pes = (const float*)d_in[4];
    const float* rsc = (const float*)d_in[5];
    float* out = (float*)d_out;

    const int smemB = NSTAGE * STAGE_B;   // 61440
    cudaFuncSetAttribute(ffn1_mma, cudaFuncAttributeMaxDynamicSharedMemorySize, smemB);
    cudaFuncSetAttribute(ffn2_mma, cudaFuncAttributeMaxDynamicSharedMemorySize, smemB);

    cudaMemsetAsync(out, 0, (size_t)out_size * sizeof(float), 0);
    init_kernel<<<1, 32>>>();
    router_kernel<<<Bt / 8, 256>>>(x, wr, rsc);
    count_kernel<<<Bt / 256, 256>>>();
    prefix_kernel<<<1, 32>>>();
    scatter_kernel<<<Bt / 256, 256>>>(pes);
    cvt_xh_kernel<<<(Bt * Dd / 4) / 256, 256>>>(x);
    cvt_wgh_kernel<<<(Ee * 2 * Hh * Dd / 4) / 256, 256>>>(wg);
    transpose_wl_kernel<<<dim3(Hh/32, Dd/32, Ee), dim3(32, 8)>>>(wl);
    ffn1_mma<<<dim3(MAX_TILES, 8), 256, smemB>>>();
    ffn2_mma<<<dim3(MAX_TILES, 2), 256, smemB>>>(out);
}

// round 17
// speedup vs baseline: 2.0103x; 1.1292x over previous
#include <cuda_runtime.h>
#include <cuda_fp16.h>
#include <math.h>
#include <stdint.h>

// Problem constants (fixed by the dataset)
#define Bt      16384
#define Dd      256
#define Hh      512
#define Ee      8
#define Kk      2
#define TILE_M  128
#define ROWS_CAP (Bt*Kk + Ee*TILE_M)     // 33792
#define MAX_TILES (ROWS_CAP / TILE_M)    // 264

#define KCH     32                        // K elems per chunk
#define LDH     40                        // smem row stride in halves (conflict-free)
#define TILE_B  (TILE_M * LDH * 2)        // 10240 bytes per tile
#define NSTAGE  3
#define STAGE_B (2 * TILE_B)              // A + B per stage
#define MF_STRIDE (16 * LDH * 2)          // 1280 bytes between A m-fragments

// prep_kernel block-range split
#define PREP_CVT_BLOCKS   ((Ee * 2 * Hh * Dd / 4) / 256)   // 2048
#define PREP_TRS_BLOCKS   ((Hh/32) * (Dd/32) * Ee)          // 1024
#define PREP_BLOCKS       (PREP_CVT_BLOCKS + PREP_TRS_BLOCKS + 1)

// ---------------- scratch ----------------
__device__ __half g_xh[(size_t)Bt * Dd];
__device__ __half g_wgh[(size_t)Ee * 2 * Hh * Dd];
__device__ __half g_wlth[(size_t)Ee * Dd * Hh];      // wl transposed: [e][d][f], half
__device__ __half g_acth[(size_t)ROWS_CAP * Hh];
__device__ int    g_tok[ROWS_CAP];
__device__ float  g_wrow[ROWS_CAP];
__device__ int    g_choice[Bt * Kk];
__device__ float  g_weight[Bt * Kk];
__device__ int    g_counts[Ee];
__device__ int    g_cursor[Ee];
__device__ int    g_pstart[Ee + 1];

// ---------------- helpers ----------------
__device__ __forceinline__ float gelu_tanh(float v) {
    const float c = 0.7978845608028654f;
    float t = tanhf(c * (v + 0.044715f * v * v * v));
    return 0.5f * v * (1.f + t);
}
__device__ __forceinline__ uint32_t smem_u32(const void* p) {
    uint32_t a;
    asm("{ .reg .u64 t; cvta.to.shared.u64 t, %1; cvt.u32.u64 %0, t; }" : "=r"(a) : "l"(p));
    return a;
}
#define CP_ASYNC16(sm, gp) asm volatile("cp.async.cg.shared.global [%0], [%1], 16;" :: "r"(sm), "l"(gp))
#define CP_COMMIT()        asm volatile("cp.async.commit_group;")
#define CP_WAIT(n)         asm volatile("cp.async.wait_group %0;" :: "n"(n))

#define LDMX4(r0, r1, r2, r3, addr) \
    asm volatile("ldmatrix.sync.aligned.m8n8.x4.shared.b16 {%0,%1,%2,%3}, [%4];" \
        : "=r"(r0), "=r"(r1), "=r"(r2), "=r"(r3) : "r"(addr))

#define MMA4(c, a0, a1, a2, a3, b0, b1) \
    asm volatile("mma.sync.aligned.m16n8k16.row.col.f32.f16.f16.f32 " \
        "{%0,%1,%2,%3},{%4,%5,%6,%7},{%8,%9},{%0,%1,%2,%3};" \
        : "+f"((c).x), "+f"((c).y), "+f"((c).z), "+f"((c).w) \
        : "r"(a0), "r"(a1), "r"(a2), "r"(a3), "r"(b0), "r"(b1))

// one K=16 step: 4 A-ldmatrix + 2 B-ldmatrix + 16 mma, all named scalars
#define K16_COMPUTE(st, k16b) do { \
    uint32_t _sa  = (st) + aoffb + (k16b); \
    uint32_t _sb  = (st) + TILE_B + boffb + (k16b); \
    uint32_t A00,A01,A02,A03, A10,A11,A12,A13, A20,A21,A22,A23, A30,A31,A32,A33; \
    uint32_t B00,B01,B10,B11, B20,B21,B30,B31; \
    LDMX4(A00,A01,A02,A03, _sa); \
    LDMX4(A10,A11,A12,A13, _sa + MF_STRIDE); \
    LDMX4(A20,A21,A22,A23, _sa + 2*MF_STRIDE); \
    LDMX4(A30,A31,A32,A33, _sa + 3*MF_STRIDE); \
    LDMX4(B00,B01,B10,B11, _sb); \
    LDMX4(B20,B21,B30,B31, _sb + MF_STRIDE); \
    MMA4(c00, A00,A01,A02,A03, B00,B01); \
    MMA4(c01, A00,A01,A02,A03, B10,B11); \
    MMA4(c02, A00,A01,A02,A03, B20,B21); \
    MMA4(c03, A00,A01,A02,A03, B30,B31); \
    MMA4(c10, A10,A11,A12,A13, B00,B01); \
    MMA4(c11, A10,A11,A12,A13, B10,B11); \
    MMA4(c12, A10,A11,A12,A13, B20,B21); \
    MMA4(c13, A10,A11,A12,A13, B30,B31); \
    MMA4(c20, A20,A21,A22,A23, B00,B01); \
    MMA4(c21, A20,A21,A22,A23, B10,B11); \
    MMA4(c22, A20,A21,A22,A23, B20,B21); \
    MMA4(c23, A20,A21,A22,A23, B30,B31); \
    MMA4(c30, A30,A31,A32,A33, B00,B01); \
    MMA4(c31, A30,A31,A32,A33, B10,B11); \
    MMA4(c32, A30,A31,A32,A33, B20,B21); \
    MMA4(c33, A30,A31,A32,A33, B30,B31); \
} while (0)

#define DECL_ACC \
    float4 c00 = make_float4(0.f,0.f,0.f,0.f), c01 = c00, c02 = c00, c03 = c00, \
           c10 = c00, c11 = c00, c12 = c00, c13 = c00, \
           c20 = c00, c21 = c00, c22 = c00, c23 = c00, \
           c30 = c00, c31 = c00, c32 = c00, c33 = c00

// ---------------- prep: init + cvt_wg + transpose_wl fused ----------------
__global__ void __launch_bounds__(256) prep_kernel(const float* __restrict__ wg,
                                                   const float* __restrict__ wl) {
    int b = blockIdx.x;
    if (b < PREP_CVT_BLOCKS) {
        // wg fp32 -> fp16
        int i = b * 256 + threadIdx.x;
        float4 v = ((const float4*)wg)[i];
        __half2* d = (__half2*)g_wgh;
        d[2*i]   = __floats2half2_rn(v.x, v.y);
        d[2*i+1] = __floats2half2_rn(v.z, v.w);
    } else if (b < PREP_CVT_BLOCKS + PREP_TRS_BLOCKS) {
        // wl (E,H,D) fp32 -> g_wlth (E,D,H) fp16; 256 threads as (32,8)
        __shared__ float tb[32][33];
        int tb_id = b - PREP_CVT_BLOCKS;
        int f0 = (tb_id & 15) * 32;            // Hh/32 = 16
        int d0 = ((tb_id >> 4) & 7) * 32;      // Dd/32 = 8
        int e  = tb_id >> 7;                   // Ee = 8
        int tx = threadIdx.x & 31, ty = threadIdx.x >> 5;
#pragma unroll
        for (int j = 0; j < 4; j++)
            tb[ty + j*8][tx] = wl[((size_t)e * Hh + (f0 + ty + j*8)) * Dd + d0 + tx];
        __syncthreads();
#pragma unroll
        for (int j = 0; j < 4; j++)
            g_wlth[((size_t)e * Dd + d0 + ty + j*8) * Hh + f0 + tx] = __float2half(tb[tx][ty + j*8]);
    } else {
        // init counters
        if (threadIdx.x < Ee) { g_counts[threadIdx.x] = 0; g_cursor[threadIdx.x] = 0; }
    }
}

// ---------------- router: RMS + logits + top2 + weights + x->fp16 + histogram ----------------
__global__ void __launch_bounds__(256) router_kernel(const float* __restrict__ x,
                                                     const float* __restrict__ wr,
                                                     const float* __restrict__ rsc) {
    __shared__ int h[Ee];
    int warp = threadIdx.x >> 5, lane = threadIdx.x & 31;
    if (threadIdx.x < Ee) h[threadIdx.x] = 0;
    __syncthreads();

    int t = blockIdx.x * 8 + warp;
    const float* xr = x + (size_t)t * Dd;
    float sumsq = 0.f;
    float l[8] = {0,0,0,0,0,0,0,0};
#pragma unroll
    for (int i = 0; i < 8; i++) {
        int d = i * 32 + lane;
        float xv = xr[d];
        g_xh[(size_t)t * Dd + d] = __float2half(xv);   // fused cvt_x
        sumsq += xv * xv;
        float xs = xv * rsc[d];
        float4 w0 = *(const float4*)(wr + d * 8);
        float4 w1 = *(const float4*)(wr + d * 8 + 4);
        l[0] += xs * w0.x; l[1] += xs * w0.y; l[2] += xs * w0.z; l[3] += xs * w0.w;
        l[4] += xs * w1.x; l[5] += xs * w1.y; l[6] += xs * w1.z; l[7] += xs * w1.w;
    }
#pragma unroll
    for (int off = 16; off; off >>= 1) {
        sumsq += __shfl_xor_sync(0xffffffffu, sumsq, off);
#pragma unroll
        for (int e = 0; e < 8; e++) l[e] += __shfl_xor_sync(0xffffffffu, l[e], off);
    }
    if (lane == 0) {
        float s = rsqrtf(sumsq * (1.f / Dd) + 1e-6f) * rsqrtf((float)Dd);
        float lg[8];
#pragma unroll
        for (int e = 0; e < 8; e++) lg[e] = l[e] * s;
        int i1 = 0;
#pragma unroll
        for (int e = 1; e < 8; e++) if (lg[e] > lg[i1]) i1 = e;
        int i2 = (i1 == 0) ? 1 : 0;
#pragma unroll
        for (int e = 0; e < 8; e++) if (e != i1 && e > i2 && lg[e] > lg[i2]) i2 = e;
        float p2 = expf(lg[i2] - lg[i1]);
        float inv = 1.f / (1.f + p2);
        g_choice[2*t] = i1;  g_choice[2*t+1] = i2;
        g_weight[2*t] = inv; g_weight[2*t+1] = p2 * inv;
        atomicAdd(&h[i1], 1);
        atomicAdd(&h[i2], 1);
    }
    __syncthreads();
    if (threadIdx.x < Ee && h[threadIdx.x] > 0)
        atomicAdd(&g_counts[threadIdx.x], h[threadIdx.x]);
}

__global__ void prefix_kernel() {
    if (threadIdx.x == 0) {
        int p = 0;
#pragma unroll
        for (int e = 0; e < Ee; e++) {
            g_pstart[e] = p;
            p += (g_counts[e] + TILE_M - 1) & ~(TILE_M - 1);
        }
        g_pstart[Ee] = p;
    }
}

__global__ void __launch_bounds__(256) scatter_kernel(const float* __restrict__ pes) {
    __shared__ int scnt[Ee];
    __shared__ int sbase[Ee];
    int tid = threadIdx.x;
    if (tid < Ee) scnt[tid] = 0;
    __syncthreads();
    int t = blockIdx.x * 256 + tid;
    int c0 = g_choice[2*t], c1 = g_choice[2*t + 1];
    int s0 = atomicAdd(&scnt[c0], 1);
    int s1 = atomicAdd(&scnt[c1], 1);
    __syncthreads();
    if (tid < Ee) sbase[tid] = atomicAdd(&g_cursor[tid], scnt[tid]);
    __syncthreads();
    int p0 = g_pstart[c0] + sbase[c0] + s0;
    int p1 = g_pstart[c1] + sbase[c1] + s1;
    g_tok[p0] = t;  g_wrow[p0] = g_weight[2*t]     * pes[c0];
    g_tok[p1] = t;  g_wrow[p1] = g_weight[2*t + 1] * pes[c1];
}

// ---------------- tile meta ----------------
__device__ __forceinline__ void tile_meta(int row0, int& e_out, int& active_out) {
    int e = -1, active = 0;
    if (row0 < g_pstart[Ee]) {
#pragma unroll
        for (int i = 0; i < Ee; i++)
            if (row0 >= g_pstart[i] && row0 < g_pstart[i + 1]) { e = i; break; }
        active = min(TILE_M, g_counts[e] - (row0 - g_pstart[e]));
    }
    e_out = e; active_out = active;
}

// ==================================================================
// ffn1: rows x Wg^T (fp16), virtual N=1024 (vc = f*2 + mat), gelu-gate -> g_acth
// grid (MAX_TILES, 8); block 256; 2 CTAs/SM
// ==================================================================
__global__ void __launch_bounds__(256, 2) ffn1_mma() {
    __shared__ int sMeta[2];
    __shared__ int sTok[TILE_M];
    extern __shared__ __half smem[];   // NSTAGE x (A | B)

    int tid = threadIdx.x;
    int row0 = blockIdx.x * TILE_M;
    int by = blockIdx.y;
    if (tid == 0) { int e, a; tile_meta(row0, e, a); sMeta[0] = e; sMeta[1] = a; }
    __syncthreads();
    int e = sMeta[0], active = sMeta[1];
    if (active <= 0) return;
    if (tid < TILE_M) sTok[tid] = (tid < active) ? g_tok[row0 + tid] : 0;
    __syncthreads();

    // loader mapping: 2 threads/row, 16 halves (32B) each
    int lrow = tid >> 1, lhalf = tid & 1;
    const __half* ag = g_xh + (size_t)sTok[lrow] * Dd + lhalf * 16;
    int vc = by * TILE_M + lrow;
    const __half* bg = g_wgh + ((size_t)(e*2 + (vc & 1)) * Hh + (vc >> 1)) * Dd + lhalf * 16;
    uint32_t sbase = smem_u32(smem);
    uint32_t lodA = (uint32_t)(lrow * LDH + lhalf * 16) * 2;
    uint32_t lodB = lodA + TILE_B;

    int lane = tid & 31, warp = tid >> 5;
    int wr = warp >> 2, wc = warp & 3;
    uint32_t aoffb = (uint32_t)(((wr*64 + (lane & 15)) * LDH + (lane >> 4) * 8) * 2);
    uint32_t boffb = (uint32_t)(((wc*32 + ((lane >> 4) & 1) * 8 + (lane & 7)) * LDH
                                 + ((lane >> 3) & 1) * 8) * 2);
    DECL_ACC;

    const int NCH = Dd / KCH;   // 8
#pragma unroll
    for (int p = 0; p < 2; p++) {
        uint32_t st = sbase + p * STAGE_B;
        CP_ASYNC16(st + lodA,      ag + p*KCH);
        CP_ASYNC16(st + lodA + 16, ag + p*KCH + 8);
        CP_ASYNC16(st + lodB,      bg + p*KCH);
        CP_ASYNC16(st + lodB + 16, bg + p*KCH + 8);
        CP_COMMIT();
    }
    for (int s = 0; s < NCH; s++) {
        if (s + 1 < NCH) { CP_WAIT(1); } else { CP_WAIT(0); }
        __syncthreads();
        if (s + 2 < NCH) {
            uint32_t st = sbase + ((s + 2) % NSTAGE) * STAGE_B;
            int k0 = (s + 2) * KCH;
            CP_ASYNC16(st + lodA,      ag + k0);
            CP_ASYNC16(st + lodA + 16, ag + k0 + 8);
            CP_ASYNC16(st + lodB,      bg + k0);
            CP_ASYNC16(st + lodB + 16, bg + k0 + 8);
            CP_COMMIT();
        }
        uint32_t st = sbase + (s % NSTAGE) * STAGE_B;
        K16_COMPUTE(st, 0);
        K16_COMPUTE(st, 32);
    }

    // epilogue: f-col gets gelu(even vc)*odd vc, stored fp16 (garbage rows finite)
    int rbase = row0 + wr*64 + (lane >> 2);
    int fbase = by*64 + wc*16 + (lane & 3);
#define EPI1(c, mf, nf) do { \
        int _r = rbase + (mf)*16; \
        int _f = fbase + (nf)*4; \
        g_acth[(size_t)_r * Hh + _f]       = __float2half(gelu_tanh((c).x) * (c).y); \
        g_acth[(size_t)(_r + 8) * Hh + _f] = __float2half(gelu_tanh((c).z) * (c).w); \
    } while (0)
    EPI1(c00,0,0); EPI1(c01,0,1); EPI1(c02,0,2); EPI1(c03,0,3);
    EPI1(c10,1,0); EPI1(c11,1,1); EPI1(c12,1,2); EPI1(c13,1,3);
    EPI1(c20,2,0); EPI1(c21,2,1); EPI1(c22,2,2); EPI1(c23,2,3);
    EPI1(c30,3,0); EPI1(c31,3,1); EPI1(c32,3,2); EPI1(c33,3,3);
#undef EPI1
}

// ==================================================================
// ffn2: act(h) x wlt[e]^T (128 x 256 x 512), scale, atomic combine into out
// grid (MAX_TILES, 2); block 256; 2 CTAs/SM
// ==================================================================
__global__ void __launch_bounds__(256, 2) ffn2_mma(float* __restrict__ out) {
    __shared__ int sMeta[2];
    __shared__ int sTok[TILE_M];
    __shared__ float sWr[TILE_M];
    extern __shared__ __half smem[];

    int tid = threadIdx.x;
    int row0 = blockIdx.x * TILE_M;
    int by = blockIdx.y;
    if (tid == 0) { int e, a; tile_meta(row0, e, a); sMeta[0] = e; sMeta[1] = a; }
    __syncthreads();
    int e = sMeta[0], active = sMeta[1];
    if (active <= 0) return;
    if (tid < TILE_M) {
        sTok[tid] = (tid < active) ? g_tok[row0 + tid] : 0;
        sWr[tid]  = (tid < active) ? g_wrow[row0 + tid] : 0.f;
    }
    __syncthreads();

    int lrow = tid >> 1, lhalf = tid & 1;
    const __half* ag = g_acth + (size_t)(row0 + lrow) * Hh + lhalf * 16;
    const __half* bg = g_wlth + ((size_t)e * Dd + by*TILE_M + lrow) * Hh + lhalf * 16;
    uint32_t sbase = smem_u32(smem);
    uint32_t lodA = (uint32_t)(lrow * LDH + lhalf * 16) * 2;
    uint32_t lodB = lodA + TILE_B;

    int lane = tid & 31, warp = tid >> 5;
    int wr = warp >> 2, wc = warp & 3;
    uint32_t aoffb = (uint32_t)(((wr*64 + (lane & 15)) * LDH + (lane >> 4) * 8) * 2);
    uint32_t boffb = (uint32_t)(((wc*32 + ((lane >> 4) & 1) * 8 + (lane & 7)) * LDH
                                 + ((lane >> 3) & 1) * 8) * 2);
    DECL_ACC;

    const int NCH = Hh / KCH;   // 16
#pragma unroll
    for (int p = 0; p < 2; p++) {
        uint32_t st = sbase + p * STAGE_B;
        CP_ASYNC16(st + lodA,      ag + p*KCH);
        CP_ASYNC16(st + lodA + 16, ag + p*KCH + 8);
        CP_ASYNC16(st + lodB,      bg + p*KCH);
        CP_ASYNC16(st + lodB + 16, bg + p*KCH + 8);
        CP_COMMIT();
    }
    for (int s = 0; s < NCH; s++) {
        if (s + 1 < NCH) { CP_WAIT(1); } else { CP_WAIT(0); }
        __syncthreads();
        if (s + 2 < NCH) {
            uint32_t st = sbase + ((s + 2) % NSTAGE) * STAGE_B;
            int k0 = (s + 2) * KCH;
            CP_ASYNC16(st + lodA,      ag + k0);
            CP_ASYNC16(st + lodA + 16, ag + k0 + 8);
            CP_ASYNC16(st + lodB,      bg + k0);
            CP_ASYNC16(st + lodB + 16, bg + k0 + 8);
            CP_COMMIT();
        }
        uint32_t st = sbase + (s % NSTAGE) * STAGE_B;
        K16_COMPUTE(st, 0);
        K16_COMPUTE(st, 32);
    }

    // epilogue: scale by wrow, atomic add into out (guard inactive rows)
    int rloc = wr*64 + (lane >> 2);
    int dbase = by*TILE_M + wc*32 + (lane & 3)*2;
#define EPI2(c, mf, nf) do { \
        int _r1 = rloc + (mf)*16; \
        if (_r1 < active) { \
            float _w = sWr[_r1]; \
            float* _ob = out + (size_t)sTok[_r1] * Dd + dbase + (nf)*8; \
            atomicAdd(_ob,     (c).x * _w); \
            atomicAdd(_ob + 1, (c).y * _w); \
        } \
        int _r2 = _r1 + 8; \
        if (_r2 < active) { \
            float _w = sWr[_r2]; \
            float* _ob = out + (size_t)sTok[_r2] * Dd + dbase + (nf)*8; \
            atomicAdd(_ob,     (c).z * _w); \
            atomicAdd(_ob + 1, (c).w * _w); \
        } \
    } while (0)
    EPI2(c00,0,0); EPI2(c01,0,1); EPI2(c02,0,2); EPI2(c03,0,3);
    EPI2(c10,1,0); EPI2(c11,1,1); EPI2(c12,1,2); EPI2(c13,1,3);
    EPI2(c20,2,0); EPI2(c21,2,1); EPI2(c22,2,2); EPI2(c23,2,3);
    EPI2(c30,3,0); EPI2(c31,3,1); EPI2(c32,3,2); EPI2(c33,3,3);
#undef EPI2
}

// ---------------- launch ----------------
extern "C" void kernel_launch(void* const* d_in, const int* in_sizes, int n_in,
                              void* d_out, int out_size) {
    const float* x   = (const float*)d_in[0];
    const float* wr  = (const float*)d_in[1];
    const float* wg  = (const float*)d_in[2];
    const float* wl  = (const float*)d_in[3];
    const float* pes = (const float*)d_in[4];
    const float* rsc = (const float*)d_in[5];
    float* out = (float*)d_out;

    const int smemB = NSTAGE * STAGE_B;   // 61440
    cudaFuncSetAttribute(ffn1_mma, cudaFuncAttributeMaxDynamicSharedMemorySize, smemB);
    cudaFuncSetAttribute(ffn2_mma, cudaFuncAttributeMaxDynamicSharedMemorySize, smemB);

    cudaMemsetAsync(out, 0, (size_t)out_size * sizeof(float), 0);
    prep_kernel<<<PREP_BLOCKS, 256>>>(wg, wl);
    router_kernel<<<Bt / 8, 256>>>(x, wr, rsc);
    prefix_kernel<<<1, 32>>>();
    scatter_kernel<<<Bt / 256, 256>>>(pes);
    ffn1_mma<<<dim3(MAX_TILES, 8), 256, smemB>>>();
    ffn2_mma<<<dim3(MAX_TILES, 2), 256, smemB>>>(out);
}